// round 10
// baseline (speedup 1.0000x reference)
#include <cuda_runtime.h>
#include <math.h>

// MoE router: logits = x @ W^T  ([16384,2048] x [2048,8]), top-2 + softmax.
// Output layout (fp32): [indices 16384*2][gates 16384*2][logits 16384*8].
//
// R9 (W in shared memory -> global-load FIFO carries only the x stream) plus
// TGRP=8: each warp batches 8 x-loads (4KB) per chunk, doubling in-flight
// DRAM bytes per warp to satisfy Little's law (~33KB/SM @ 577cyc).
// Each warp handles exactly one 8-token group -> no tail imbalance.

#define DDIM 2048
#define NEXP 8
#define TGRP 8
#define CHUNKS (DDIM / 128)       // 16 chunks of 128 floats (4 per lane)
#define W_FLOATS (NEXP * DDIM)    // 16384
#define SMEM_BYTES (W_FLOATS * 4) // 65536
#define NBLOCK 296

__global__ __launch_bounds__(256, 2)
void router_kernel(const float* __restrict__ x,
                   const float* __restrict__ w,
                   float* __restrict__ out,
                   int n_tokens, int groups_total)
{
    extern __shared__ float ws[];   // [NEXP][DDIM]

    // Cooperative W load: 4096 float4s over 256 threads = 16 each.
    {
        const float4* wsrc = reinterpret_cast<const float4*>(w);
        float4* wdst = reinterpret_cast<float4*>(ws);
        #pragma unroll
        for (int i = 0; i < W_FLOATS / 4 / 256; i++)
            wdst[threadIdx.x + i * 256] = wsrc[threadIdx.x + i * 256];
    }
    __syncthreads();

    const int lane = threadIdx.x & 31;
    const int wid  = threadIdx.x >> 5;

    // One group per warp, spread so every block keeps 6-7 active warps.
    const int g = blockIdx.x + NBLOCK * wid;
    if (g >= groups_total) return;

    float* out_idx    = out;
    float* out_gate   = out + (size_t)n_tokens * 2;
    float* out_logits = out + (size_t)n_tokens * 4;

    const float* wsl = ws + lane * 4;
    const int tok0 = g * TGRP;
    const float* xp = x + (size_t)tok0 * DDIM + lane * 4;

    float acc[TGRP][NEXP];
    #pragma unroll
    for (int t = 0; t < TGRP; t++)
        #pragma unroll
        for (int e = 0; e < NEXP; e++)
            acc[t][e] = 0.0f;

    #pragma unroll 1
    for (int c = 0; c < CHUNKS; c++) {
        float4 xv[TGRP];
        #pragma unroll
        for (int t = 0; t < TGRP; t++)
            xv[t] = *reinterpret_cast<const float4*>(xp + (size_t)t * DDIM + c * 128);
        #pragma unroll
        for (int e = 0; e < NEXP; e++) {
            float4 wv = *reinterpret_cast<const float4*>(wsl + e * DDIM + c * 128);
            #pragma unroll
            for (int t = 0; t < TGRP; t++) {
                acc[t][e] = fmaf(xv[t].x, wv.x,
                            fmaf(xv[t].y, wv.y,
                            fmaf(xv[t].z, wv.z,
                            fmaf(xv[t].w, wv.w, acc[t][e]))));
            }
        }
    }

    // Full butterfly reduction: every lane ends with the complete sums.
    #pragma unroll
    for (int t = 0; t < TGRP; t++) {
        #pragma unroll
        for (int e = 0; e < NEXP; e++) {
            float v = acc[t][e];
            v += __shfl_xor_sync(0xffffffffu, v, 16);
            v += __shfl_xor_sync(0xffffffffu, v, 8);
            v += __shfl_xor_sync(0xffffffffu, v, 4);
            v += __shfl_xor_sync(0xffffffffu, v, 2);
            v += __shfl_xor_sync(0xffffffffu, v, 1);
            acc[t][e] = v;
        }
    }

    if (lane < TGRP) {
        const int tok = tok0 + lane;
        // Predicated token select (no dynamic register indexing).
        float v[NEXP];
        #pragma unroll
        for (int e = 0; e < NEXP; e++) {
            float s = acc[0][e];
            if (lane == 1) s = acc[1][e];
            if (lane == 2) s = acc[2][e];
            if (lane == 3) s = acc[3][e];
            if (lane == 4) s = acc[4][e];
            if (lane == 5) s = acc[5][e];
            if (lane == 6) s = acc[6][e];
            if (lane == 7) s = acc[7][e];
            v[e] = s;
        }

        // logits (two 16B stores)
        *reinterpret_cast<float4*>(out_logits + (size_t)tok * NEXP) =
            make_float4(v[0], v[1], v[2], v[3]);
        *reinterpret_cast<float4*>(out_logits + (size_t)tok * NEXP + 4) =
            make_float4(v[4], v[5], v[6], v[7]);

        // top-2 (ties -> lower index, matching jax.lax.top_k)
        int i0 = 0; float v0 = v[0];
        #pragma unroll
        for (int e = 1; e < NEXP; e++)
            if (v[e] > v0) { v0 = v[e]; i0 = e; }
        int i1 = -1; float v1 = -INFINITY;
        #pragma unroll
        for (int e = 0; e < NEXP; e++)
            if (e != i0 && v[e] > v1) { v1 = v[e]; i1 = e; }

        // softmax over [v0, v1] with v0 = max
        float ex = __expf(v1 - v0);
        float g0 = 1.0f / (1.0f + ex);
        float g1 = ex * g0;

        *reinterpret_cast<float2*>(out_idx  + (size_t)tok * 2) =
            make_float2((float)i0, (float)i1);
        *reinterpret_cast<float2*>(out_gate + (size_t)tok * 2) =
            make_float2(g0, g1);
    }
}

extern "C" void kernel_launch(void* const* d_in, const int* in_sizes, int n_in,
                              void* d_out, int out_size)
{
    const float* x = (const float*)d_in[0];
    const float* w = (const float*)d_in[1];
    float* out = (float*)d_out;

    const int n_tokens = in_sizes[0] / DDIM;     // 16384
    const int groups   = n_tokens / TGRP;        // 2048

    cudaFuncSetAttribute(router_kernel,
                         cudaFuncAttributeMaxDynamicSharedMemorySize,
                         SMEM_BYTES);

    router_kernel<<<NBLOCK, 256, SMEM_BYTES>>>(x, w, out, n_tokens, groups);
}

// round 11
// speedup vs baseline: 1.0205x; 1.0205x over previous
#include <cuda_runtime.h>
#include <math.h>

// MoE router: logits = x @ W^T  ([16384,2048] x [2048,8]), top-2 + softmax.
// Output layout (fp32): [indices 16384*2][gates 16384*2][logits 16384*8].
//
// R9 base (W in shared memory so the global-load FIFO carries only the x
// stream) + explicit software pipeline: xv is double-buffered in registers,
// and each iteration issues chunk c+1's 4 LDG.128s BEFORE the FMA chain of
// chunk c. Loads are always in flight during compute -> no per-warp MLP
// duty-cycle bubble (the limiter measured in R9/R10).

#define DDIM 2048
#define NEXP 8
#define TGRP 4
#define CHUNKS (DDIM / 128)       // 16 chunks of 128 floats (4 per lane)
#define W_FLOATS (NEXP * DDIM)    // 16384
#define SMEM_BYTES (W_FLOATS * 4) // 65536
#define NBLOCK 296

__global__ __launch_bounds__(256, 2)
void router_kernel(const float* __restrict__ x,
                   const float* __restrict__ w,
                   float* __restrict__ out,
                   int n_tokens, int groups_total)
{
    extern __shared__ float ws[];   // [NEXP][DDIM]

    // Cooperative W load: 4096 float4s over 256 threads = 16 each.
    {
        const float4* wsrc = reinterpret_cast<const float4*>(w);
        float4* wdst = reinterpret_cast<float4*>(ws);
        #pragma unroll
        for (int i = 0; i < W_FLOATS / 4 / 256; i++)
            wdst[threadIdx.x + i * 256] = wsrc[threadIdx.x + i * 256];
    }
    __syncthreads();

    const int lane  = threadIdx.x & 31;
    const int warp  = (blockIdx.x * blockDim.x + threadIdx.x) >> 5;
    const int nwarp = (gridDim.x * blockDim.x) >> 5;

    float* out_idx    = out;
    float* out_gate   = out + (size_t)n_tokens * 2;
    float* out_logits = out + (size_t)n_tokens * 4;

    const float* wsl = ws + lane * 4;

    for (int g = warp; g < groups_total; g += nwarp) {
        const int tok0 = g * TGRP;
        const float* xp = x + (size_t)tok0 * DDIM + lane * 4;

        float acc[TGRP][NEXP];
        #pragma unroll
        for (int t = 0; t < TGRP; t++)
            #pragma unroll
            for (int e = 0; e < NEXP; e++)
                acc[t][e] = 0.0f;

        // Software pipeline: prologue loads chunk 0; each iteration issues
        // chunk c+1's loads, then computes chunk c.
        float4 xv_cur[TGRP], xv_nxt[TGRP];
        #pragma unroll
        for (int t = 0; t < TGRP; t++)
            xv_cur[t] = *reinterpret_cast<const float4*>(xp + (size_t)t * DDIM);

        #pragma unroll 2
        for (int c = 0; c < CHUNKS; c++) {
            if (c + 1 < CHUNKS) {
                #pragma unroll
                for (int t = 0; t < TGRP; t++)
                    xv_nxt[t] = *reinterpret_cast<const float4*>(
                        xp + (size_t)t * DDIM + (c + 1) * 128);
            }
            #pragma unroll
            for (int e = 0; e < NEXP; e++) {
                float4 wv = *reinterpret_cast<const float4*>(wsl + e * DDIM + c * 128);
                #pragma unroll
                for (int t = 0; t < TGRP; t++) {
                    acc[t][e] = fmaf(xv_cur[t].x, wv.x,
                                fmaf(xv_cur[t].y, wv.y,
                                fmaf(xv_cur[t].z, wv.z,
                                fmaf(xv_cur[t].w, wv.w, acc[t][e]))));
                }
            }
            #pragma unroll
            for (int t = 0; t < TGRP; t++)
                xv_cur[t] = xv_nxt[t];
        }

        // Full butterfly reduction: every lane ends with the complete sums.
        #pragma unroll
        for (int t = 0; t < TGRP; t++) {
            #pragma unroll
            for (int e = 0; e < NEXP; e++) {
                float v = acc[t][e];
                v += __shfl_xor_sync(0xffffffffu, v, 16);
                v += __shfl_xor_sync(0xffffffffu, v, 8);
                v += __shfl_xor_sync(0xffffffffu, v, 4);
                v += __shfl_xor_sync(0xffffffffu, v, 2);
                v += __shfl_xor_sync(0xffffffffu, v, 1);
                acc[t][e] = v;
            }
        }

        if (lane < TGRP) {
            const int tok = tok0 + lane;
            // Predicated token select (no dynamic register indexing).
            float v[NEXP];
            #pragma unroll
            for (int e = 0; e < NEXP; e++) {
                float s = acc[0][e];
                if (lane == 1) s = acc[1][e];
                if (lane == 2) s = acc[2][e];
                if (lane == 3) s = acc[3][e];
                v[e] = s;
            }

            // logits (two 16B stores)
            *reinterpret_cast<float4*>(out_logits + (size_t)tok * NEXP) =
                make_float4(v[0], v[1], v[2], v[3]);
            *reinterpret_cast<float4*>(out_logits + (size_t)tok * NEXP + 4) =
                make_float4(v[4], v[5], v[6], v[7]);

            // top-2 (ties -> lower index, matching jax.lax.top_k)
            int i0 = 0; float v0 = v[0];
            #pragma unroll
            for (int e = 1; e < NEXP; e++)
                if (v[e] > v0) { v0 = v[e]; i0 = e; }
            int i1 = -1; float v1 = -INFINITY;
            #pragma unroll
            for (int e = 0; e < NEXP; e++)
                if (e != i0 && v[e] > v1) { v1 = v[e]; i1 = e; }

            // softmax over [v0, v1] with v0 = max
            float ex = __expf(v1 - v0);
            float g0 = 1.0f / (1.0f + ex);
            float g1 = ex * g0;

            *reinterpret_cast<float2*>(out_idx  + (size_t)tok * 2) =
                make_float2((float)i0, (float)i1);
            *reinterpret_cast<float2*>(out_gate + (size_t)tok * 2) =
                make_float2(g0, g1);
        }
    }
}

extern "C" void kernel_launch(void* const* d_in, const int* in_sizes, int n_in,
                              void* d_out, int out_size)
{
    const float* x = (const float*)d_in[0];
    const float* w = (const float*)d_in[1];
    float* out = (float*)d_out;

    const int n_tokens = in_sizes[0] / DDIM;     // 16384
    const int groups   = n_tokens / TGRP;        // 4096

    cudaFuncSetAttribute(router_kernel,
                         cudaFuncAttributeMaxDynamicSharedMemorySize,
                         SMEM_BYTES);

    router_kernel<<<NBLOCK, 256, SMEM_BYTES>>>(x, w, out, n_tokens, groups);
}